// round 5
// baseline (speedup 1.0000x reference)
#include <cuda_runtime.h>
#include <cuda_fp16.h>
#include <cstdint>
#include <math.h>

#define D       128
#define NMAX    8192
#define TAU_INV 10.0f
#define EX2K    14.4269504088896f   // TAU_INV * log2(e)
#define TM      128
#define TN      256
#define JSPLIT  2

// scratch (device globals; no allocation allowed)
__device__ __half g_ph[NMAX * D];      // normalized rows, f16 (MMA operands)
__device__ float  g_pf[NMAX * D];      // normalized rows, fp32 (pos-sum pass)
__device__ int    g_y2[NMAX];
__device__ float  g_S[NMAX];           // exp-sum accumulators
__device__ float  g_cls[2][D];         // per-class vector sums (fp32)
__device__ int    g_cnt[2];            // per-class counts
__device__ float  g_L[NMAX];           // per-row loss

// ---------------------------------------------------------------------------
__device__ __forceinline__ uint32_t smem_u32(const void* p) {
    uint32_t a;
    asm("{ .reg .u64 t; cvta.to.shared.u64 t, %1; cvt.u32.u64 %0, t; }"
        : "=r"(a) : "l"(p));
    return a;
}
__device__ __forceinline__ void ldsm4(uint32_t r[4], uint32_t addr) {
    asm volatile("ldmatrix.sync.aligned.m8n8.x4.shared.b16 {%0,%1,%2,%3}, [%4];"
                 : "=r"(r[0]), "=r"(r[1]), "=r"(r[2]), "=r"(r[3]) : "r"(addr));
}
__device__ __forceinline__ void mma16816(float c[4], const uint32_t a[4],
                                         const uint32_t b[2]) {
    asm volatile(
        "mma.sync.aligned.m16n8k16.row.col.f32.f16.f16.f32 "
        "{%0,%1,%2,%3}, {%4,%5,%6,%7}, {%8,%9}, {%0,%1,%2,%3};"
        : "+f"(c[0]), "+f"(c[1]), "+f"(c[2]), "+f"(c[3])
        : "r"(a[0]), "r"(a[1]), "r"(a[2]), "r"(a[3]), "r"(b[0]), "r"(b[1]));
}
__device__ __forceinline__ void cp16(uint32_t saddr, const void* g) {
    asm volatile("cp.async.cg.shared.global [%0], [%1], 16;"
                 :: "r"(saddr), "l"(g) : "memory");
}
__device__ __forceinline__ float ex2(float x) {
    float r;
    asm("ex2.approx.f32 %0, %1;" : "=f"(r) : "f"(x));
    return r;
}
#define CP_COMMIT() asm volatile("cp.async.commit_group;" ::: "memory")

#define A_OFF  0u
#define B_OFF  32768u                    // two 64 KB B buffers
#define SMEM_TOTAL (32768 + 2 * 65536)

// ---------------------------------------------------------------------------
// Kernel 0: zero class accumulators
// ---------------------------------------------------------------------------
__global__ void zero_kernel() {
    int t = threadIdx.x;
    if (t < 2 * D) ((float*)g_cls)[t] = 0.f;
    if (t < 2) g_cnt[t] = 0;
}

// ---------------------------------------------------------------------------
// Kernel 1: normalize rows -> f16 + fp32 tables; class sums; zero g_S.
// 8 rows per block (one per warp), 256 threads.
// ---------------------------------------------------------------------------
__global__ void prep_kernel(const float* __restrict__ zi,
                            const float* __restrict__ zj,
                            const int*   __restrict__ y, int B) {
    __shared__ float cls_s[2][D];
    __shared__ int   cnt_s[2];
    int warp = threadIdx.x >> 5, lane = threadIdx.x & 31;
    int t = threadIdx.x;
    if (t < 2 * D) ((float*)cls_s)[t] = 0.f;
    if (t < 2) cnt_s[t] = 0;
    __syncthreads();

    int row  = blockIdx.x * 8 + warp;
    const float* src = (row < B) ? (zi + (size_t)row * D)
                                 : (zj + (size_t)(row - B) * D);
    float4 v = ((const float4*)src)[lane];
    float ss = v.x * v.x + v.y * v.y + v.z * v.z + v.w * v.w;
    #pragma unroll
    for (int o = 16; o > 0; o >>= 1) ss += __shfl_xor_sync(0xffffffffu, ss, o);
    float s = 1.f / fmaxf(sqrtf(ss), 1e-8f);
    float4 pn = make_float4(v.x * s, v.y * s, v.z * s, v.w * s);

    ((float4*)(g_pf + (size_t)row * D))[lane] = pn;
    __half2 h0 = __floats2half2_rn(pn.x, pn.y);
    __half2 h1 = __floats2half2_rn(pn.z, pn.w);
    uint2 u;
    u.x = *reinterpret_cast<unsigned int*>(&h0);
    u.y = *reinterpret_cast<unsigned int*>(&h1);
    ((uint2*)(g_ph + (size_t)row * D))[lane] = u;

    int lbl = y[(row < B) ? row : (row - B)];
    if (lane == 0) {
        g_y2[row] = lbl;
        g_S[row]  = 0.f;
        atomicAdd(&cnt_s[lbl], 1);
    }
    atomicAdd(&cls_s[lbl][lane * 4 + 0], pn.x);
    atomicAdd(&cls_s[lbl][lane * 4 + 1], pn.y);
    atomicAdd(&cls_s[lbl][lane * 4 + 2], pn.z);
    atomicAdd(&cls_s[lbl][lane * 4 + 3], pn.w);
    __syncthreads();
    if (t < 2 * D) atomicAdd(&((float*)g_cls)[t], ((float*)cls_s)[t]);
    if (t < 2)     atomicAdd(&g_cnt[t], cnt_s[t]);
}

// ---------------------------------------------------------------------------
// Kernel 2: HMMA GEMM, epilogue = pure exp2-sum (diag masked in 1 tile).
// 512 threads = 16 warps (2 m x 8 n). Warp tile 64x32. B double-buffered.
// ---------------------------------------------------------------------------
__global__ __launch_bounds__(512, 1)
void main_kernel() {
    extern __shared__ char sm[];
    const uint32_t smb = smem_u32(sm);

    const int tid = threadIdx.x, lane = tid & 31, wid = tid >> 5;
    const int warp_m = wid >> 3, warp_n = wid & 7;
    const int rowTile = blockIdx.x >> 1, split = blockIdx.x & 1;
    const int rowBase = rowTile * TM;
    const int NT = NMAX / TN / JSPLIT;  // 16

    // ---- A tile (128 x 128 f16), xor-swizzled ------------------------------
    for (int u = tid; u < TM * 16; u += 512) {
        int r = u >> 4, c = u & 15;
        uint4 v = ((const uint4*)(g_ph + (size_t)(rowBase + r) * D))[c];
        *(uint4*)(sm + A_OFF + (uint32_t)r * 256u + (uint32_t)((c ^ (r & 7)) << 4)) = v;
    }

    // ---- prefetch B tile 0 --------------------------------------------------
    {
        int jbase = split * TN;
        for (int u = tid; u < TN * 16; u += 512) {
            int r = u >> 4, c = u & 15;
            cp16(smb + B_OFF + (uint32_t)r * 256u + (uint32_t)((c ^ (r & 7)) << 4),
                 g_ph + (size_t)(jbase + r) * D + c * 8);
        }
        CP_COMMIT();
    }

    // ---- ldmatrix address precompute ----------------------------------------
    const int g = lane >> 3;
    uint32_t a_off[4], a_msk[4];
    #pragma unroll
    for (int mt = 0; mt < 4; mt++) {
        int row = warp_m * 64 + mt * 16 + (g & 1) * 8 + (lane & 7);
        a_off[mt] = smb + A_OFF + (uint32_t)row * 256u;
        a_msk[mt] = (uint32_t)(row & 7);
    }
    const int a_cadd = g >> 1;
    uint32_t b_row[2], b_msk[2];
    #pragma unroll
    for (int nt2 = 0; nt2 < 2; nt2++) {
        int row = warp_n * 32 + nt2 * 16 + (g >> 1) * 8 + (lane & 7);
        b_row[nt2] = (uint32_t)row * 256u;
        b_msk[nt2] = (uint32_t)(row & 7);
    }
    const int b_cadd = g & 1;

    const int irow0 = rowBase + warp_m * 64 + (lane >> 2);
    float es[8];
    #pragma unroll
    for (int s = 0; s < 8; s++) es[s] = 0.f;

    // ---- main j loop ---------------------------------------------------------
    for (int t = 0; t < NT; t++) {
        __syncthreads();
        if (t + 1 < NT) {
            int jb = ((t + 1) * JSPLIT + split) * TN;
            uint32_t boff = B_OFF + ((t + 1) & 1) * 65536u;
            for (int u = tid; u < TN * 16; u += 512) {
                int r = u >> 4, c = u & 15;
                cp16(smb + boff + (uint32_t)r * 256u + (uint32_t)((c ^ (r & 7)) << 4),
                     g_ph + (size_t)(jb + r) * D + c * 8);
            }
            CP_COMMIT();
            asm volatile("cp.async.wait_group 1;" ::: "memory");
        } else {
            asm volatile("cp.async.wait_group 0;" ::: "memory");
        }
        __syncthreads();

        const int buf   = t & 1;
        const int jbase = (t * JSPLIT + split) * TN;
        const uint32_t bbase = smb + B_OFF + (uint32_t)buf * 65536u;

        float acc[4][4][4];
        #pragma unroll
        for (int mt = 0; mt < 4; mt++)
            #pragma unroll
            for (int nt = 0; nt < 4; nt++)
                #pragma unroll
                for (int k = 0; k < 4; k++) acc[mt][nt][k] = 0.f;

        #pragma unroll
        for (int ks = 0; ks < 8; ks++) {
            uint32_t af[4][4], bf[2][4];
            #pragma unroll
            for (int mt = 0; mt < 4; mt++)
                ldsm4(af[mt], a_off[mt] +
                      (uint32_t)(((2 * ks + a_cadd) ^ a_msk[mt]) << 4));
            #pragma unroll
            for (int nt2 = 0; nt2 < 2; nt2++)
                ldsm4(bf[nt2], bbase + b_row[nt2] +
                      (uint32_t)(((2 * ks + b_cadd) ^ b_msk[nt2]) << 4));
            #pragma unroll
            for (int mt = 0; mt < 4; mt++)
                #pragma unroll
                for (int nt = 0; nt < 4; nt++)
                    mma16816(acc[mt][nt], af[mt], &bf[nt >> 1][(nt & 1) * 2]);
        }

        // ---- epilogue: exp2 accumulation only --------------------------------
        if (rowBase >= jbase && rowBase < jbase + TN) {
            // diagonal tile: mask j == i
            #pragma unroll
            for (int nt = 0; nt < 4; nt++) {
                int j0 = jbase + warp_n * 32 + nt * 8 + (lane & 3) * 2;
                #pragma unroll
                for (int mt = 0; mt < 4; mt++) {
                    #pragma unroll
                    for (int q = 0; q < 4; q++) {
                        int jj = j0 + (q & 1);
                        int ii = irow0 + mt * 16 + (q < 2 ? 0 : 8);
                        float e = ex2(acc[mt][nt][q] * EX2K);
                        if (jj != ii) es[mt * 2 + (q >> 1)] += e;
                    }
                }
            }
        } else {
            #pragma unroll
            for (int nt = 0; nt < 4; nt++)
                #pragma unroll
                for (int mt = 0; mt < 4; mt++)
                    #pragma unroll
                    for (int q = 0; q < 4; q++)
                        es[mt * 2 + (q >> 1)] += ex2(acc[mt][nt][q] * EX2K);
        }
    }

    // ---- lane-group reduce + atomics ----------------------------------------
    #pragma unroll
    for (int s = 0; s < 8; s++) {
        float e = es[s];
        e += __shfl_xor_sync(0xffffffffu, e, 1);
        e += __shfl_xor_sync(0xffffffffu, e, 2);
        if ((lane & 3) == 0) {
            int row = rowBase + warp_m * 64 + (s >> 1) * 16 + (lane >> 2) + (s & 1) * 8;
            atomicAdd(&g_S[row], e);
        }
    }
}

// ---------------------------------------------------------------------------
// Kernel 3: per-row loss: ps_i = (pn_i . S_{yi} - pn_i . pn_i) / tau,
//           cn_i = cnt[yi]-1,  L_i = -(ps_i/cn_i - log(es_i))
// one warp per row, 4 rows per warp-iteration stride.
// ---------------------------------------------------------------------------
__global__ void finalize1_kernel() {
    int gw   = (blockIdx.x * blockDim.x + threadIdx.x) >> 5;  // global warp id
    int lane = threadIdx.x & 31;
    int nw   = (gridDim.x * blockDim.x) >> 5;
    for (int row = gw; row < NMAX; row += nw) {
        int lbl = g_y2[row];
        float4 v = ((const float4*)(g_pf + (size_t)row * D))[lane];
        float4 c = ((const float4*)(g_cls[lbl]))[lane];
        float dotS  = v.x * c.x + v.y * c.y + v.z * c.z + v.w * c.w;
        float selfd = v.x * v.x + v.y * v.y + v.z * v.z + v.w * v.w;
        #pragma unroll
        for (int o = 16; o > 0; o >>= 1) {
            dotS  += __shfl_xor_sync(0xffffffffu, dotS, o);
            selfd += __shfl_xor_sync(0xffffffffu, selfd, o);
        }
        if (lane == 0) {
            float ps = TAU_INV * (dotS - selfd);
            float cn = (float)(g_cnt[lbl] - 1);
            g_L[row] = -(ps / cn - logf(g_S[row]));
        }
    }
}

// ---------------------------------------------------------------------------
// Kernel 4: scalar reduce
// ---------------------------------------------------------------------------
__global__ void finalize2_kernel(float* __restrict__ out) {
    int t = threadIdx.x;  // 256
    float local = 0.f;
    for (int i = t; i < NMAX; i += 256) local += g_L[i];
    #pragma unroll
    for (int o = 16; o > 0; o >>= 1) local += __shfl_xor_sync(0xffffffffu, local, o);
    __shared__ float ws[8];
    if ((t & 31) == 0) ws[t >> 5] = local;
    __syncthreads();
    if (t < 8) {
        float v = ws[t];
        #pragma unroll
        for (int o = 4; o > 0; o >>= 1) v += __shfl_xor_sync(0x000000ffu, v, o);
        if (t == 0) out[0] = v;
    }
}

// ---------------------------------------------------------------------------
extern "C" void kernel_launch(void* const* d_in, const int* in_sizes, int n_in,
                              void* d_out, int out_size) {
    const float* zi = (const float*)d_in[0];
    const float* zj = (const float*)d_in[1];
    const int*   y  = (const int*)d_in[2];
    int B = in_sizes[2];
    int N = 2 * B;

    zero_kernel<<<1, 256>>>();
    prep_kernel<<<N / 8, 256>>>(zi, zj, y, B);

    cudaFuncSetAttribute(main_kernel, cudaFuncAttributeMaxDynamicSharedMemorySize,
                         SMEM_TOTAL);
    main_kernel<<<(N / TM) * JSPLIT, 512, SMEM_TOTAL>>>();

    finalize1_kernel<<<128, 256>>>();
    finalize2_kernel<<<1, 256>>>((float*)d_out);
}

// round 6
// speedup vs baseline: 2.1890x; 2.1890x over previous
#include <cuda_runtime.h>
#include <cuda_fp16.h>
#include <cstdint>
#include <math.h>

#define D       128
#define NMAX    8192
#define TAU_INV 10.0f
#define EX2K    14.4269504088896f   // TAU_INV * log2(e)
#define TM      128
#define NTT     64                  // N / TM tile count per dim
#define NTILES_TRI (NTT * (NTT + 1) / 2)   // 2080

// scratch (device globals; no allocation allowed)
__device__ __half g_ph[NMAX * D];      // normalized rows, f16 (MMA operands)
__device__ float  g_pf[NMAX * D];      // normalized rows, fp32
__device__ int    g_y2[NMAX];
__device__ float  g_S[NMAX];           // exp-sum accumulators
__device__ float  g_cls[2][D];         // per-class vector sums
__device__ int    g_cnt[2];

// ---------------------------------------------------------------------------
__device__ __forceinline__ uint32_t smem_u32(const void* p) {
    uint32_t a;
    asm("{ .reg .u64 t; cvta.to.shared.u64 t, %1; cvt.u32.u64 %0, t; }"
        : "=r"(a) : "l"(p));
    return a;
}
__device__ __forceinline__ void ldsm4(uint32_t r[4], uint32_t addr) {
    asm volatile("ldmatrix.sync.aligned.m8n8.x4.shared.b16 {%0,%1,%2,%3}, [%4];"
                 : "=r"(r[0]), "=r"(r[1]), "=r"(r[2]), "=r"(r[3]) : "r"(addr));
}
__device__ __forceinline__ void mma16816(float c[4], const uint32_t a[4],
                                         const uint32_t b[2]) {
    asm volatile(
        "mma.sync.aligned.m16n8k16.row.col.f32.f16.f16.f32 "
        "{%0,%1,%2,%3}, {%4,%5,%6,%7}, {%8,%9}, {%0,%1,%2,%3};"
        : "+f"(c[0]), "+f"(c[1]), "+f"(c[2]), "+f"(c[3])
        : "r"(a[0]), "r"(a[1]), "r"(a[2]), "r"(a[3]), "r"(b[0]), "r"(b[1]));
}
__device__ __forceinline__ void cp16(uint32_t saddr, const void* g) {
    asm volatile("cp.async.cg.shared.global [%0], [%1], 16;"
                 :: "r"(saddr), "l"(g) : "memory");
}
__device__ __forceinline__ float ex2(float x) {
    float r;
    asm("ex2.approx.f32 %0, %1;" : "=f"(r) : "f"(x));
    return r;
}
#define CP_COMMIT() asm volatile("cp.async.commit_group;" ::: "memory")
#define CP_WAIT0()  asm volatile("cp.async.wait_group 0;" ::: "memory")

#define A_OFF  0u
#define B_OFF  32768u
#define SMEM_TOTAL 65536

// ---------------------------------------------------------------------------
// Kernel 0: zero class accumulators + output scalar
// ---------------------------------------------------------------------------
__global__ void zero_kernel(float* __restrict__ out) {
    int t = threadIdx.x;
    if (t < 2 * D) ((float*)g_cls)[t] = 0.f;
    if (t < 2) g_cnt[t] = 0;
    if (t == 0) out[0] = 0.f;
}

// ---------------------------------------------------------------------------
// Kernel 1: normalize rows -> f16 + fp32 tables; class sums; zero g_S.
// ---------------------------------------------------------------------------
__global__ void prep_kernel(const float* __restrict__ zi,
                            const float* __restrict__ zj,
                            const int*   __restrict__ y, int B) {
    __shared__ float cls_s[2][D];
    __shared__ int   cnt_s[2];
    int warp = threadIdx.x >> 5, lane = threadIdx.x & 31;
    int t = threadIdx.x;
    if (t < 2 * D) ((float*)cls_s)[t] = 0.f;
    if (t < 2) cnt_s[t] = 0;
    __syncthreads();

    int row  = blockIdx.x * 8 + warp;
    const float* src = (row < B) ? (zi + (size_t)row * D)
                                 : (zj + (size_t)(row - B) * D);
    float4 v = ((const float4*)src)[lane];
    float ss = v.x * v.x + v.y * v.y + v.z * v.z + v.w * v.w;
    #pragma unroll
    for (int o = 16; o > 0; o >>= 1) ss += __shfl_xor_sync(0xffffffffu, ss, o);
    float s = 1.f / fmaxf(sqrtf(ss), 1e-8f);
    float4 pn = make_float4(v.x * s, v.y * s, v.z * s, v.w * s);

    ((float4*)(g_pf + (size_t)row * D))[lane] = pn;
    __half2 h0 = __floats2half2_rn(pn.x, pn.y);
    __half2 h1 = __floats2half2_rn(pn.z, pn.w);
    uint2 u;
    u.x = *reinterpret_cast<unsigned int*>(&h0);
    u.y = *reinterpret_cast<unsigned int*>(&h1);
    ((uint2*)(g_ph + (size_t)row * D))[lane] = u;

    int lbl = y[(row < B) ? row : (row - B)];
    if (lane == 0) {
        g_y2[row] = lbl;
        g_S[row]  = 0.f;
        atomicAdd(&cnt_s[lbl], 1);
    }
    atomicAdd(&cls_s[lbl][lane * 4 + 0], pn.x);
    atomicAdd(&cls_s[lbl][lane * 4 + 1], pn.y);
    atomicAdd(&cls_s[lbl][lane * 4 + 2], pn.z);
    atomicAdd(&cls_s[lbl][lane * 4 + 3], pn.w);
    __syncthreads();
    if (t < 2 * D) atomicAdd(&((float*)g_cls)[t], ((float*)cls_s)[t]);
    if (t < 2)     atomicAdd(&g_cnt[t], cnt_s[t]);
}

// ---------------------------------------------------------------------------
// Kernel 2: symmetric HMMA. One 128x128 tile per CTA, colTile >= rowTile.
// Off-diag tiles feed BOTH row sums and column sums of exp(sim).
// 256 threads = 8 warps (2m x 4n), warp tile 64x32.
// ---------------------------------------------------------------------------
__global__ __launch_bounds__(256, 2)
void main_kernel() {
    extern __shared__ char sm[];
    __shared__ float rs[TM], cs[TM];
    const uint32_t smb = smem_u32(sm);

    const int tid = threadIdx.x, lane = tid & 31, wid = tid >> 5;
    const int warp_m = wid >> 2, warp_n = wid & 3;

    // ---- triangular decode: idx -> (r, c), c >= r ---------------------------
    int idx = blockIdx.x;
    int r = (int)((2.0f * NTT + 1.0f -
                   sqrtf((2.0f * NTT + 1.0f) * (2.0f * NTT + 1.0f) - 8.0f * idx)) * 0.5f);
    // start(r) = r*(2*NTT - r + 1)/2 ; fix up fp rounding
    while (r > 0 && r * (2 * NTT - r + 1) / 2 > idx) r--;
    while ((r + 1) * (2 * NTT - r) / 2 <= idx) r++;
    const int c = r + (idx - r * (2 * NTT - r + 1) / 2);
    const int rowBase = r * TM, colBase = c * TM;
    const bool isdiag = (r == c);

    // ---- load A (rows) and B (cols) tiles, xor-swizzled, via cp.async -------
    for (int u = tid; u < TM * 16; u += 256) {
        int rr = u >> 4, cc = u & 15;
        uint32_t sw = (uint32_t)rr * 256u + (uint32_t)((cc ^ (rr & 7)) << 4);
        cp16(smb + A_OFF + sw, g_ph + (size_t)(rowBase + rr) * D + cc * 8);
        cp16(smb + B_OFF + sw, g_ph + (size_t)(colBase + rr) * D + cc * 8);
    }
    CP_COMMIT();
    if (tid < TM) { rs[tid] = 0.f; cs[tid] = 0.f; }

    // ---- ldmatrix address precompute ----------------------------------------
    const int g = lane >> 3;
    uint32_t a_off[4], a_msk[4];
    #pragma unroll
    for (int mt = 0; mt < 4; mt++) {
        int row = warp_m * 64 + mt * 16 + (g & 1) * 8 + (lane & 7);
        a_off[mt] = smb + A_OFF + (uint32_t)row * 256u;
        a_msk[mt] = (uint32_t)(row & 7);
    }
    const int a_cadd = g >> 1;
    uint32_t b_row[2], b_msk[2];
    #pragma unroll
    for (int nt2 = 0; nt2 < 2; nt2++) {
        int row = warp_n * 32 + nt2 * 16 + (g >> 1) * 8 + (lane & 7);
        b_row[nt2] = (uint32_t)row * 256u;
        b_msk[nt2] = (uint32_t)(row & 7);
    }
    const int b_cadd = g & 1;

    CP_WAIT0();
    __syncthreads();

    // ---- GEMM ----------------------------------------------------------------
    float acc[4][4][4];
    #pragma unroll
    for (int mt = 0; mt < 4; mt++)
        #pragma unroll
        for (int nt = 0; nt < 4; nt++)
            #pragma unroll
            for (int k = 0; k < 4; k++) acc[mt][nt][k] = 0.f;

    #pragma unroll
    for (int ks = 0; ks < 8; ks++) {
        uint32_t af[4][4], bf[2][4];
        #pragma unroll
        for (int mt = 0; mt < 4; mt++)
            ldsm4(af[mt], a_off[mt] + (uint32_t)(((2 * ks + a_cadd) ^ a_msk[mt]) << 4));
        #pragma unroll
        for (int nt2 = 0; nt2 < 2; nt2++)
            ldsm4(bf[nt2], smb + B_OFF + b_row[nt2] +
                  (uint32_t)(((2 * ks + b_cadd) ^ b_msk[nt2]) << 4));
        #pragma unroll
        for (int mt = 0; mt < 4; mt++)
            #pragma unroll
            for (int nt = 0; nt < 4; nt++)
                mma16816(acc[mt][nt], af[mt], &bf[nt >> 1][(nt & 1) * 2]);
    }

    // ---- epilogue: exp2, row sums + column sums ------------------------------
    const int lrow0 = warp_m * 64 + (lane >> 2);
    float es[8], csl[8];
    #pragma unroll
    for (int s = 0; s < 8; s++) { es[s] = 0.f; csl[s] = 0.f; }

    #pragma unroll
    for (int nt = 0; nt < 4; nt++) {
        #pragma unroll
        for (int mt = 0; mt < 4; mt++) {
            #pragma unroll
            for (int q = 0; q < 4; q++) {
                float e = ex2(acc[mt][nt][q] * EX2K);
                if (isdiag) {
                    int jl = warp_n * 32 + nt * 8 + (lane & 3) * 2 + (q & 1);
                    int il = lrow0 + mt * 16 + ((q < 2) ? 0 : 8);
                    if (jl == il) e = 0.f;
                }
                es[mt * 2 + (q >> 1)] += e;
                csl[nt * 2 + (q & 1)] += e;
            }
        }
    }

    // row sums: reduce over lane&3 (columns), smem-accumulate across warp_n
    #pragma unroll
    for (int s = 0; s < 8; s++) {
        float e = es[s];
        e += __shfl_xor_sync(0xffffffffu, e, 1);
        e += __shfl_xor_sync(0xffffffffu, e, 2);
        if ((lane & 3) == 0)
            atomicAdd(&rs[warp_m * 64 + (s >> 1) * 16 + (lane >> 2) + (s & 1) * 8], e);
    }
    // column sums: reduce over lane>>2 (rows), smem-accumulate across warp_m
    if (!isdiag) {
        #pragma unroll
        for (int s = 0; s < 8; s++) {
            float v = csl[s];
            v += __shfl_xor_sync(0xffffffffu, v, 4);
            v += __shfl_xor_sync(0xffffffffu, v, 8);
            v += __shfl_xor_sync(0xffffffffu, v, 16);
            if (lane < 4)
                atomicAdd(&cs[warp_n * 32 + (s >> 1) * 8 + lane * 2 + (s & 1)], v);
        }
    }
    __syncthreads();

    if (tid < TM)            atomicAdd(&g_S[rowBase + tid], rs[tid]);
    else if (!isdiag)        atomicAdd(&g_S[colBase + tid - TM], cs[tid - TM]);
}

// ---------------------------------------------------------------------------
// Kernel 3: fused per-row loss + global sum into out (out pre-zeroed).
// 1024 blocks x 256 thr: one row per warp.
// ---------------------------------------------------------------------------
__global__ void finalize_kernel(float* __restrict__ out) {
    __shared__ float bsum;
    int warp = threadIdx.x >> 5, lane = threadIdx.x & 31;
    if (threadIdx.x == 0) bsum = 0.f;
    __syncthreads();

    int row = blockIdx.x * 8 + warp;
    int lbl = g_y2[row];
    float4 v = ((const float4*)(g_pf + (size_t)row * D))[lane];
    float4 cc = ((const float4*)(g_cls[lbl]))[lane];
    float dotS  = v.x * cc.x + v.y * cc.y + v.z * cc.z + v.w * cc.w;
    float selfd = v.x * v.x + v.y * v.y + v.z * v.z + v.w * v.w;
    #pragma unroll
    for (int o = 16; o > 0; o >>= 1) {
        dotS  += __shfl_xor_sync(0xffffffffu, dotS, o);
        selfd += __shfl_xor_sync(0xffffffffu, selfd, o);
    }
    if (lane == 0) {
        float ps = TAU_INV * (dotS - selfd);
        float cn = (float)(g_cnt[lbl] - 1);
        atomicAdd(&bsum, -(ps / cn - logf(g_S[row])));
    }
    __syncthreads();
    if (threadIdx.x == 0) atomicAdd(out, bsum);
}

// ---------------------------------------------------------------------------
extern "C" void kernel_launch(void* const* d_in, const int* in_sizes, int n_in,
                              void* d_out, int out_size) {
    const float* zi = (const float*)d_in[0];
    const float* zj = (const float*)d_in[1];
    const int*   y  = (const int*)d_in[2];
    int B = in_sizes[2];
    int N = 2 * B;

    zero_kernel<<<1, 256>>>((float*)d_out);
    prep_kernel<<<N / 8, 256>>>(zi, zj, y, B);

    cudaFuncSetAttribute(main_kernel, cudaFuncAttributeMaxDynamicSharedMemorySize,
                         SMEM_TOTAL);
    main_kernel<<<NTILES_TRI, 256, SMEM_TOTAL>>>();

    finalize_kernel<<<N / 8, 256>>>((float*)d_out);
}

// round 8
// speedup vs baseline: 2.5319x; 1.1567x over previous
#include <cuda_runtime.h>
#include <cuda_fp16.h>
#include <cstdint>
#include <math.h>

#define D       128
#define NMAX    8192
#define TAU_INV 10.0f
#define EX2K    14.4269504088896f   // TAU_INV * log2(e)
#define TM      128
#define NTT     64                  // tiles per dimension
#define NTILES_TRI (NTT * (NTT + 1) / 2)   // 2080
#define GMAIN   296                 // 2 CTAs per SM, persistent

// scratch (device globals; no allocation allowed)
__device__ __half g_ph[NMAX * D];      // normalized rows, f16
__device__ int    g_y2[NMAX];
__device__ float  g_S[NMAX];           // exp-sum accumulators
__device__ float  g_cls[2][D];         // per-class vector sums
__device__ int    g_cnt[2];

// ---------------------------------------------------------------------------
__device__ __forceinline__ uint32_t smem_u32(const void* p) {
    uint32_t a;
    asm("{ .reg .u64 t; cvta.to.shared.u64 t, %1; cvt.u32.u64 %0, t; }"
        : "=r"(a) : "l"(p));
    return a;
}
__device__ __forceinline__ void ldsm4(uint32_t r[4], uint32_t addr) {
    asm volatile("ldmatrix.sync.aligned.m8n8.x4.shared.b16 {%0,%1,%2,%3}, [%4];"
                 : "=r"(r[0]), "=r"(r[1]), "=r"(r[2]), "=r"(r[3]) : "r"(addr));
}
__device__ __forceinline__ void mma16816(float c[4], const uint32_t a[4],
                                         const uint32_t b[2]) {
    asm volatile(
        "mma.sync.aligned.m16n8k16.row.col.f32.f16.f16.f32 "
        "{%0,%1,%2,%3}, {%4,%5,%6,%7}, {%8,%9}, {%0,%1,%2,%3};"
        : "+f"(c[0]), "+f"(c[1]), "+f"(c[2]), "+f"(c[3])
        : "r"(a[0]), "r"(a[1]), "r"(a[2]), "r"(a[3]), "r"(b[0]), "r"(b[1]));
}
__device__ __forceinline__ void cp16(uint32_t saddr, const void* g) {
    asm volatile("cp.async.cg.shared.global [%0], [%1], 16;"
                 :: "r"(saddr), "l"(g) : "memory");
}
__device__ __forceinline__ float ex2(float x) {
    float r;
    asm("ex2.approx.f32 %0, %1;" : "=f"(r) : "f"(x));
    return r;
}
#define CP_COMMIT() asm volatile("cp.async.commit_group;" ::: "memory")
#define CP_WAIT(n)  asm volatile("cp.async.wait_group %0;" :: "n"(n) : "memory")

#define A_OFF  0u
#define B0_OFF 32768u
#define B1_OFF 65536u
#define SMEM_TOTAL 98304

// ---------------------------------------------------------------------------
// Kernel 0: zero class accumulators + output scalar
// ---------------------------------------------------------------------------
__global__ void zero_kernel(float* __restrict__ out) {
    int t = threadIdx.x;
    if (t < 2 * D) ((float*)g_cls)[t] = 0.f;
    if (t < 2) g_cnt[t] = 0;
    if (t == 0) out[0] = 0.f;
}

// ---------------------------------------------------------------------------
// Kernel 1: normalize rows -> f16 table; class sums; zero g_S.
// ---------------------------------------------------------------------------
__global__ void prep_kernel(const float* __restrict__ zi,
                            const float* __restrict__ zj,
                            const int*   __restrict__ y, int B) {
    __shared__ float cls_s[2][D];
    __shared__ int   cnt_s[2];
    int warp = threadIdx.x >> 5, lane = threadIdx.x & 31;
    int t = threadIdx.x;
    if (t < 2 * D) ((float*)cls_s)[t] = 0.f;
    if (t < 2) cnt_s[t] = 0;
    __syncthreads();

    int row  = blockIdx.x * 8 + warp;
    const float* src = (row < B) ? (zi + (size_t)row * D)
                                 : (zj + (size_t)(row - B) * D);
    float4 v = ((const float4*)src)[lane];
    float ss = v.x * v.x + v.y * v.y + v.z * v.z + v.w * v.w;
    #pragma unroll
    for (int o = 16; o > 0; o >>= 1) ss += __shfl_xor_sync(0xffffffffu, ss, o);
    float s = 1.f / fmaxf(sqrtf(ss), 1e-8f);
    float4 pn = make_float4(v.x * s, v.y * s, v.z * s, v.w * s);

    __half2 h0 = __floats2half2_rn(pn.x, pn.y);
    __half2 h1 = __floats2half2_rn(pn.z, pn.w);
    uint2 u;
    u.x = *reinterpret_cast<unsigned int*>(&h0);
    u.y = *reinterpret_cast<unsigned int*>(&h1);
    ((uint2*)(g_ph + (size_t)row * D))[lane] = u;

    int lbl = y[(row < B) ? row : (row - B)];
    if (lane == 0) {
        g_y2[row] = lbl;
        g_S[row]  = 0.f;
        atomicAdd(&cnt_s[lbl], 1);
    }
    atomicAdd(&cls_s[lbl][lane * 4 + 0], pn.x);
    atomicAdd(&cls_s[lbl][lane * 4 + 1], pn.y);
    atomicAdd(&cls_s[lbl][lane * 4 + 2], pn.z);
    atomicAdd(&cls_s[lbl][lane * 4 + 3], pn.w);
    __syncthreads();
    if (t < 2 * D) atomicAdd(&((float*)g_cls)[t], ((float*)cls_s)[t]);
    if (t < 2)     atomicAdd(&g_cnt[t], cnt_s[t]);
}

// ---------------------------------------------------------------------------
__device__ __forceinline__ void load_tile(uint32_t dst, int base, int tid) {
    for (int u = tid; u < TM * 16; u += 256) {
        int rr = u >> 4, cc = u & 15;
        cp16(dst + (uint32_t)rr * 256u + (uint32_t)((cc ^ (rr & 7)) << 4),
             g_ph + (size_t)(base + rr) * D + cc * 8);
    }
}

// ---------------------------------------------------------------------------
// Kernel 2: persistent symmetric HMMA. 296 CTAs, contiguous triangular chunks.
// A-panel reused; B double-buffered. Row exp-sums in registers, flushed per
// panel (accr tracks the owning panel); col sums via spread global atomics.
// ---------------------------------------------------------------------------
__global__ __launch_bounds__(256, 2)
void main_kernel() {
    extern __shared__ char sm[];
    const uint32_t smb = smem_u32(sm);

    const int tid = threadIdx.x, lane = tid & 31, wid = tid >> 5;
    const int warp_m = wid >> 2, warp_n = wid & 3;

    const int lo = (int)(((long long)blockIdx.x * NTILES_TRI) / GMAIN);
    const int hi = (int)(((long long)(blockIdx.x + 1) * NTILES_TRI) / GMAIN);

    // decode starting (r, c)
    int r = 0;
    while ((r + 1) * (2 * NTT - r) / 2 <= lo) r++;
    int c = r + (lo - r * (2 * NTT - r + 1) / 2);

    load_tile(smb + A_OFF, r * TM, tid);
    load_tile(smb + B0_OFF, c * TM, tid);
    CP_COMMIT();

    // ldsm address precompute
    const int g = lane >> 3;
    uint32_t a_off[4], a_msk[4];
    #pragma unroll
    for (int mt = 0; mt < 4; mt++) {
        int row = warp_m * 64 + mt * 16 + (g & 1) * 8 + (lane & 7);
        a_off[mt] = smb + A_OFF + (uint32_t)row * 256u;
        a_msk[mt] = (uint32_t)(row & 7);
    }
    const int a_cadd = g >> 1;
    uint32_t b_row[2], b_msk[2];
    #pragma unroll
    for (int nt2 = 0; nt2 < 2; nt2++) {
        int row = warp_n * 32 + nt2 * 16 + (g >> 1) * 8 + (lane & 7);
        b_row[nt2] = (uint32_t)row * 256u;
        b_msk[nt2] = (uint32_t)(row & 7);
    }
    const int b_cadd = g & 1;

    float es[8];
    #pragma unroll
    for (int s = 0; s < 8; s++) es[s] = 0.f;
    int parity = 0;
    int accr = r;                 // row panel owning the es[] accumulations

    for (int t = lo; t < hi; t++) {
        const int tr = r, tc = c;
        const bool isdiag = (tr == tc);
        int nr = r, nc = c + 1;
        if (nc == NTT) { nr = r + 1; nc = nr; }
        const bool havenext = (t + 1 < hi);

        __syncthreads();
        if (havenext) {
            load_tile(smb + (parity ? B0_OFF : B1_OFF), nc * TM, tid);
            CP_COMMIT();
            CP_WAIT(1);
        } else {
            CP_WAIT(0);
        }
        __syncthreads();

        // ---- GEMM ----------------------------------------------------------
        const uint32_t bbase = smb + (parity ? B1_OFF : B0_OFF);
        float acc[4][4][4];
        #pragma unroll
        for (int mt = 0; mt < 4; mt++)
            #pragma unroll
            for (int nt = 0; nt < 4; nt++)
                #pragma unroll
                for (int k = 0; k < 4; k++) acc[mt][nt][k] = 0.f;

        #pragma unroll
        for (int ks = 0; ks < 8; ks++) {
            uint32_t af[4][4], bf[2][4];
            #pragma unroll
            for (int mt = 0; mt < 4; mt++)
                ldsm4(af[mt], a_off[mt] +
                      (uint32_t)(((2 * ks + a_cadd) ^ a_msk[mt]) << 4));
            #pragma unroll
            for (int nt2 = 0; nt2 < 2; nt2++)
                ldsm4(bf[nt2], bbase + b_row[nt2] +
                      (uint32_t)(((2 * ks + b_cadd) ^ b_msk[nt2]) << 4));
            #pragma unroll
            for (int mt = 0; mt < 4; mt++)
                #pragma unroll
                for (int nt = 0; nt < 4; nt++)
                    mma16816(acc[mt][nt], af[mt], &bf[nt >> 1][(nt & 1) * 2]);
        }

        // ---- epilogue ---------------------------------------------------------
        float csl[8];
        #pragma unroll
        for (int s = 0; s < 8; s++) csl[s] = 0.f;
        #pragma unroll
        for (int nt = 0; nt < 4; nt++) {
            #pragma unroll
            for (int mt = 0; mt < 4; mt++) {
                #pragma unroll
                for (int q = 0; q < 4; q++) {
                    float e = ex2(acc[mt][nt][q] * EX2K);
                    if (isdiag) {
                        int jl = warp_n * 32 + nt * 8 + (lane & 3) * 2 + (q & 1);
                        int il = warp_m * 64 + mt * 16 + (lane >> 2) + ((q < 2) ? 0 : 8);
                        if (jl == il) e = 0.f;
                    }
                    es[mt * 2 + (q >> 1)] += e;
                    csl[nt * 2 + (q & 1)] += e;
                }
            }
        }
        // column sums -> global atomics (skip for diag: row path covers it)
        if (!isdiag) {
            int colBase = tc * TM;
            #pragma unroll
            for (int s = 0; s < 8; s++) {
                float v = csl[s];
                v += __shfl_xor_sync(0xffffffffu, v, 4);
                v += __shfl_xor_sync(0xffffffffu, v, 8);
                v += __shfl_xor_sync(0xffffffffu, v, 16);
                if (lane < 4)
                    atomicAdd(&g_S[colBase + warp_n * 32 + (s >> 1) * 8 + lane * 2 + (s & 1)], v);
            }
        }

        // ---- row-panel change while continuing: flush es, reload A ------------
        if (havenext && nr != tr) {
            int rowBase = accr * TM;
            #pragma unroll
            for (int s = 0; s < 8; s++) {
                float e = es[s];
                e += __shfl_xor_sync(0xffffffffu, e, 1);
                e += __shfl_xor_sync(0xffffffffu, e, 2);
                if ((lane & 3) == 0)
                    atomicAdd(&g_S[rowBase + warp_m * 64 + (s >> 1) * 16 +
                                   (lane >> 2) + (s & 1) * 8], e);
                es[s] = 0.f;
            }
            accr = nr;
            __syncthreads();   // all warps done reading A
            load_tile(smb + A_OFF, nr * TM, tid);
            CP_COMMIT();
        }
        r = nr; c = nc; parity ^= 1;
    }

    // final row flush — accr still owns the es[] accumulations
    {
        int rowBase = accr * TM;
        #pragma unroll
        for (int s = 0; s < 8; s++) {
            float e = es[s];
            e += __shfl_xor_sync(0xffffffffu, e, 1);
            e += __shfl_xor_sync(0xffffffffu, e, 2);
            if ((lane & 3) == 0)
                atomicAdd(&g_S[rowBase + warp_m * 64 + (s >> 1) * 16 +
                               (lane >> 2) + (s & 1) * 8], e);
        }
    }
}

// ---------------------------------------------------------------------------
// Kernel 3: loss = sum_i log S_i  -  tau_inv * sum_c (||S_c||^2 - cnt_c)/(cnt_c-1)
// ---------------------------------------------------------------------------
__global__ void finalize_kernel(float* __restrict__ out) {
    __shared__ float ws[8];
    int t = threadIdx.x, lane = t & 31, warp = t >> 5;
    int row = blockIdx.x * 256 + t;
    float local = logf(g_S[row]);
    #pragma unroll
    for (int o = 16; o > 0; o >>= 1) local += __shfl_xor_sync(0xffffffffu, local, o);
    if (lane == 0) ws[warp] = local;
    __syncthreads();
    if (t < 8) {
        float v = ws[t];
        #pragma unroll
        for (int o = 4; o > 0; o >>= 1) v += __shfl_xor_sync(0x000000ffu, v, o);
        if (t == 0) atomicAdd(out, v);
    }
    // class term (block 0, warps 0-1: one class each)
    if (blockIdx.x == 0 && warp < 2) {
        float4 cv = ((const float4*)(g_cls[warp]))[lane];
        float nsq = cv.x * cv.x + cv.y * cv.y + cv.z * cv.z + cv.w * cv.w;
        #pragma unroll
        for (int o = 16; o > 0; o >>= 1) nsq += __shfl_xor_sync(0xffffffffu, nsq, o);
        if (lane == 0) {
            float cnt = (float)g_cnt[warp];
            atomicAdd(out, -TAU_INV * (nsq - cnt) / (cnt - 1.f));
        }
    }
}

// ---------------------------------------------------------------------------
extern "C" void kernel_launch(void* const* d_in, const int* in_sizes, int n_in,
                              void* d_out, int out_size) {
    const float* zi = (const float*)d_in[0];
    const float* zj = (const float*)d_in[1];
    const int*   y  = (const int*)d_in[2];
    int B = in_sizes[2];
    int N = 2 * B;

    zero_kernel<<<1, 256>>>((float*)d_out);
    prep_kernel<<<N / 8, 256>>>(zi, zj, y, B);

    cudaFuncSetAttribute(main_kernel, cudaFuncAttributeMaxDynamicSharedMemorySize,
                         SMEM_TOTAL);
    main_kernel<<<GMAIN, 256, SMEM_TOTAL>>>();

    finalize_kernel<<<N / 256, 256>>>((float*)d_out);
}